// round 1
// baseline (speedup 1.0000x reference)
#include <cuda_runtime.h>

// Problem constants
#define NB     2
#define NL     8192
#define NHID   1024
#define NSTATE 16
#define USTR   3072            // u channel stride = 3*HID
#define CHUNK  64
#define NCHUNK (NL / CHUNK)    // 128
#define CHB    128             // channels per block

// Per-chunk carry scratch: [chunk][b*HID + c][32]  (0..15 = fwd, 16..31 = bwd)
__device__ float g_carr[(size_t)NCHUNK * NB * NHID * 32];

__device__ __forceinline__ float ldu(const float* __restrict__ ub, int t, int uc) {
    return (t >= 0 && t < NL) ? ub[(size_t)t * USTR + uc] : 0.0f;
}

__device__ __forceinline__ float dot16(const float* r, const float* F) {
    float s0 = 0.f, s1 = 0.f, s2 = 0.f, s3 = 0.f;
#pragma unroll
    for (int m = 0; m < 4; m++) {
        s0 = fmaf(r[m],      F[m],      s0);
        s1 = fmaf(r[m + 4],  F[m + 4],  s1);
        s2 = fmaf(r[m + 8],  F[m + 8],  s2);
        s3 = fmaf(r[m + 12], F[m + 12], s3);
    }
    return (s0 + s1) + (s2 + s3);
}

// ---------------------------------------------------------------------------
// K1: per-chunk forward/backward mode aggregates of x1v
//   Sf_m = sum_i p^(C-1-i) x[i]   (chunk-end forward state, zero-seeded)
//   Sb_m = sum_i p^i x[i]         (chunk-start backward state, zero-seeded)
// ---------------------------------------------------------------------------
__global__ void __launch_bounds__(CHB)
k1_chunk_sums(const float* __restrict__ u, const float* __restrict__ w,
              const float* __restrict__ logp)
{
    const int j = blockIdx.x;
    const int c = blockIdx.y * CHB + threadIdx.x;
    const int b = blockIdx.z;
    const int hh = c >> 6, d = c & 63;
    const int uc1 = hh * 192 + 64 + d;    // x1 source channel
    const int ucv = hh * 192 + 128 + d;   // v  source channel
    const float* ub = u + (size_t)b * NL * USTR;

    const float w1a = w[uc1 * 3 + 0], w1b = w[uc1 * 3 + 1], w1c = 2.0f * w[uc1 * 3 + 2];
    const float wva = w[ucv * 3 + 0], wvb = w[ucv * 3 + 1], wvc = 2.0f * w[ucv * 3 + 2];

    float p[NSTATE], Sf[NSTATE], Sb[NSTATE], pw[NSTATE];
#pragma unroll
    for (int m = 0; m < NSTATE; m++) {
        p[m] = expf(logp[m]); Sf[m] = 0.f; Sb[m] = 0.f; pw[m] = 1.f;
    }

    const int t0 = j * CHUNK;
    float a0 = ldu(ub, t0 - 2, uc1), a1 = ldu(ub, t0 - 1, uc1), a2 = ldu(ub, t0, uc1),
          a3 = ldu(ub, t0 + 1, uc1), a4 = ldu(ub, t0 + 2, uc1);
    float e0 = ldu(ub, t0 - 2, ucv), e1 = ldu(ub, t0 - 1, ucv), e2 = ldu(ub, t0, ucv),
          e3 = ldu(ub, t0 + 1, ucv), e4 = ldu(ub, t0 + 2, ucv);

#pragma unroll 4
    for (int i = 0; i < CHUNK; i++) {
        float z1 = fmaf(w1a, a0 + a4, fmaf(w1b, a1 + a3, w1c * a2));
        float zv = fmaf(wva, e0 + e4, fmaf(wvb, e1 + e3, wvc * e2));
        float x  = z1 * zv;
#pragma unroll
        for (int m = 0; m < NSTATE; m++) Sf[m] = fmaf(p[m], Sf[m], x);
#pragma unroll
        for (int m = 0; m < NSTATE; m++) { Sb[m] = fmaf(pw[m], x, Sb[m]); pw[m] *= p[m]; }
        a0 = a1; a1 = a2; a2 = a3; a3 = a4; a4 = ldu(ub, t0 + i + 3, uc1);
        e0 = e1; e1 = e2; e2 = e3; e3 = e4; e4 = ldu(ub, t0 + i + 3, ucv);
    }

    float* dst = g_carr + ((size_t)j * (NB * NHID) + (size_t)b * NHID + c) * 32;
#pragma unroll
    for (int m = 0; m < NSTATE; m++) { dst[m] = Sf[m]; dst[16 + m] = Sb[m]; }
}

// ---------------------------------------------------------------------------
// K2: in-place affine exclusive scan across chunks per (b,c,mode,dir).
//   fwd: Cf[0]=0; Cf[j] = q*Cf[j-1] + Sf[j-1]
//   bwd: Cb[NC-1]=0; Cb[j] = q*Cb[j+1] + Sb[j+1]      (q = p^CHUNK)
// ---------------------------------------------------------------------------
__global__ void k2_scan(const float* __restrict__ logp)
{
    const int tid = blockIdx.x * blockDim.x + threadIdx.x;
    if (tid >= NB * NHID * 32) return;
    const int dirm = tid & 31;
    const int bc   = tid >> 5;
    const int m    = dirm & 15;
    const int dir  = dirm >> 4;
    const float q  = expf(logp[m] * (float)CHUNK);

    const size_t stride = (size_t)(NB * NHID) * 32;
    float* base = g_carr + (size_t)bc * 32 + dirm;
    float carry = 0.0f;
    if (dir == 0) {
        for (int j = 0; j < NCHUNK; j++) {
            float s = base[(size_t)j * stride];
            base[(size_t)j * stride] = carry;
            carry = fmaf(q, carry, s);
        }
    } else {
        for (int j = NCHUNK - 1; j >= 0; j--) {
            float s = base[(size_t)j * stride];
            base[(size_t)j * stride] = carry;
            carry = fmaf(q, carry, s);
        }
    }
}

// ---------------------------------------------------------------------------
// K3: descending sweep (backward recurrence, seed Cb) -> smem partial,
//     ascending sweep (forward recurrence, seed Cf) -> combine, gate by x2.
// ---------------------------------------------------------------------------
__global__ void __launch_bounds__(CHB)
k3_apply(const float* __restrict__ u, const float* __restrict__ w,
         const float* __restrict__ logp, const float* __restrict__ resid,
         const float* __restrict__ Dp, float* __restrict__ out)
{
    __shared__ float ysm[CHUNK * CHB];   // 32 KB, thread-private columns

    const int j = blockIdx.x;
    const int c = blockIdx.y * CHB + threadIdx.x;
    const int b = blockIdx.z;
    const int hh = c >> 6, d = c & 63;
    const int uc2 = hh * 192 + d;        // x2
    const int uc1 = uc2 + 64;            // x1
    const int ucv = uc2 + 128;           // v
    const float* ub = u + (size_t)b * NL * USTR;

    const float w1a = w[uc1 * 3 + 0], w1b = w[uc1 * 3 + 1], w1c = 2.0f * w[uc1 * 3 + 2];
    const float wva = w[ucv * 3 + 0], wvb = w[ucv * 3 + 1], wvc = 2.0f * w[ucv * 3 + 2];
    const float w2a = w[uc2 * 3 + 0], w2b = w[uc2 * 3 + 1], w2c = 2.0f * w[uc2 * 3 + 2];

    float p[NSTATE], r[NSTATE];
#pragma unroll
    for (int m = 0; m < NSTATE; m++) { p[m] = expf(logp[m]); r[m] = resid[m]; }
    const float Dc = Dp[c];

    const float* cp = g_carr + ((size_t)j * (NB * NHID) + (size_t)b * NHID + c) * 32;
    const int t0 = j * CHUNK;
    const int t1 = t0 + CHUNK - 1;

    // ---- sweep 1: descending (backward recurrence) ----
    float Bk[NSTATE];
#pragma unroll
    for (int m = 0; m < NSTATE; m++) Bk[m] = cp[16 + m];

    float a0 = ldu(ub, t1 - 2, uc1), a1 = ldu(ub, t1 - 1, uc1), a2 = ldu(ub, t1, uc1),
          a3 = ldu(ub, t1 + 1, uc1), a4 = ldu(ub, t1 + 2, uc1);
    float e0 = ldu(ub, t1 - 2, ucv), e1 = ldu(ub, t1 - 1, ucv), e2 = ldu(ub, t1, ucv),
          e3 = ldu(ub, t1 + 1, ucv), e4 = ldu(ub, t1 + 2, ucv);

#pragma unroll 4
    for (int i = CHUNK - 1; i >= 0; i--) {
        float z1 = fmaf(w1a, a0 + a4, fmaf(w1b, a1 + a3, w1c * a2));
        float zv = fmaf(wva, e0 + e4, fmaf(wvb, e1 + e3, wvc * e2));
        float x  = z1 * zv;
#pragma unroll
        for (int m = 0; m < NSTATE; m++) Bk[m] = fmaf(p[m], Bk[m], x);
        ysm[i * CHB + threadIdx.x] = fmaf(Dc, x, dot16(r, Bk));
        a4 = a3; a3 = a2; a2 = a1; a1 = a0; a0 = ldu(ub, t0 + i - 3, uc1);
        e4 = e3; e3 = e2; e2 = e1; e1 = e0; e0 = ldu(ub, t0 + i - 3, ucv);
    }

    // ---- sweep 2: ascending (forward recurrence + output gate) ----
    float F[NSTATE];
#pragma unroll
    for (int m = 0; m < NSTATE; m++) F[m] = cp[m];

    a0 = ldu(ub, t0 - 2, uc1); a1 = ldu(ub, t0 - 1, uc1); a2 = ldu(ub, t0, uc1);
    a3 = ldu(ub, t0 + 1, uc1); a4 = ldu(ub, t0 + 2, uc1);
    e0 = ldu(ub, t0 - 2, ucv); e1 = ldu(ub, t0 - 1, ucv); e2 = ldu(ub, t0, ucv);
    e3 = ldu(ub, t0 + 1, ucv); e4 = ldu(ub, t0 + 2, ucv);
    float g0 = ldu(ub, t0 - 2, uc2), g1 = ldu(ub, t0 - 1, uc2), g2 = ldu(ub, t0, uc2),
          g3 = ldu(ub, t0 + 1, uc2), g4 = ldu(ub, t0 + 2, uc2);

#pragma unroll 4
    for (int i = 0; i < CHUNK; i++) {
        float z1 = fmaf(w1a, a0 + a4, fmaf(w1b, a1 + a3, w1c * a2));
        float zv = fmaf(wva, e0 + e4, fmaf(wvb, e1 + e3, wvc * e2));
        float z2 = fmaf(w2a, g0 + g4, fmaf(w2b, g1 + g3, w2c * g2));
        float x  = z1 * zv;
#pragma unroll
        for (int m = 0; m < NSTATE; m++) F[m] = fmaf(p[m], F[m], x);
        float y = dot16(r, F) + ysm[i * CHB + threadIdx.x];
        out[((size_t)b * NL + (t0 + i)) * NHID + c] = y * z2;
        a0 = a1; a1 = a2; a2 = a3; a3 = a4; a4 = ldu(ub, t0 + i + 3, uc1);
        e0 = e1; e1 = e2; e2 = e3; e3 = e4; e4 = ldu(ub, t0 + i + 3, ucv);
        g0 = g1; g1 = g2; g2 = g3; g3 = g4; g4 = ldu(ub, t0 + i + 3, uc2);
    }
}

// ---------------------------------------------------------------------------
extern "C" void kernel_launch(void* const* d_in, const int* in_sizes, int n_in,
                              void* d_out, int out_size)
{
    const float* u     = (const float*)d_in[0];
    const float* w     = (const float*)d_in[1];
    const float* logp  = (const float*)d_in[2];
    const float* resid = (const float*)d_in[3];
    const float* Dp    = (const float*)d_in[4];
    float* out = (float*)d_out;

    dim3 grid(NCHUNK, NHID / CHB, NB);   // (128, 8, 2)
    k1_chunk_sums<<<grid, CHB>>>(u, w, logp);

    const int nscan = NB * NHID * 32;    // 65536
    k2_scan<<<(nscan + 255) / 256, 256>>>(logp);

    k3_apply<<<grid, CHB>>>(u, w, logp, resid, Dp, out);
}

// round 2
// speedup vs baseline: 1.4053x; 1.4053x over previous
#include <cuda_runtime.h>

// Problem constants
#define NB     2
#define NL     8192
#define NHID   1024
#define NSTATE 16
#define USTR   3072            // u channel stride = 3*HID
#define CHUNK  64
#define NCHUNK (NL / CHUNK)    // 128
#define CHB    128             // channels per block

// Per-chunk carry scratch: [chunk][b*HID + c][32]  (0..15 = fwd, 16..31 = bwd)
__device__ float g_carr[(size_t)NCHUNK * NB * NHID * 32];
// Materialized x1v: [b][t][c]
__device__ float g_xv[(size_t)NB * NL * NHID];

// ---- packed fp32x2 helpers (sm_103a FFMA2 path, PTX-only) ----
typedef unsigned long long u64;

__device__ __forceinline__ u64 pk2(float lo, float hi) {
    u64 r; asm("mov.b64 %0,{%1,%2};" : "=l"(r) : "f"(lo), "f"(hi)); return r;
}
__device__ __forceinline__ float2 up2(u64 v) {
    float2 r; asm("mov.b64 {%0,%1},%2;" : "=f"(r.x), "=f"(r.y) : "l"(v)); return r;
}
__device__ __forceinline__ u64 fma2_(u64 a, u64 b, u64 c) {
    u64 d; asm("fma.rn.f32x2 %0,%1,%2,%3;" : "=l"(d) : "l"(a), "l"(b), "l"(c)); return d;
}
__device__ __forceinline__ u64 mul2_(u64 a, u64 b) {
    u64 d; asm("mul.rn.f32x2 %0,%1,%2;" : "=l"(d) : "l"(a), "l"(b)); return d;
}
__device__ __forceinline__ u64 add2_(u64 a, u64 b) {
    u64 d; asm("add.rn.f32x2 %0,%1,%2;" : "=l"(d) : "l"(a), "l"(b)); return d;
}

__device__ __forceinline__ float ldu(const float* __restrict__ ub, int t, int uc) {
    return (t >= 0 && t < NL) ? ub[(size_t)t * USTR + uc] : 0.0f;
}

// ---------------------------------------------------------------------------
// K1: compute x1v via symmetric 5-tap FIR, store to g_xv, and emit per-chunk
//     forward/backward mode aggregates (packed f32x2, 8-deep load batching).
// ---------------------------------------------------------------------------
__global__ void __launch_bounds__(CHB)
k1_chunk_sums(const float* __restrict__ u, const float* __restrict__ w,
              const float* __restrict__ logp)
{
    const int j = blockIdx.x;
    const int c = blockIdx.y * CHB + threadIdx.x;
    const int b = blockIdx.z;
    const int hh = c >> 6, d = c & 63;
    const int uc1 = hh * 192 + 64 + d;    // x1 source channel
    const int ucv = hh * 192 + 128 + d;   // v  source channel
    const float* ub = u + (size_t)b * NL * USTR;
    float* xvp = g_xv + ((size_t)b * NL) * NHID + c;

    const float w1a = w[uc1 * 3 + 0], w1b = w[uc1 * 3 + 1], w1c = 2.0f * w[uc1 * 3 + 2];
    const float wva = w[ucv * 3 + 0], wvb = w[ucv * 3 + 1], wvc = 2.0f * w[ucv * 3 + 2];

    u64 p2[8], Sf[8], Sb[8], pw[8];
#pragma unroll
    for (int m = 0; m < 8; m++) {
        p2[m] = pk2(expf(logp[2 * m]), expf(logp[2 * m + 1]));
        Sf[m] = 0ULL; Sb[m] = 0ULL; pw[m] = pk2(1.0f, 1.0f);
    }

    const int t0 = j * CHUNK;
    float a0 = ldu(ub, t0 - 2, uc1), a1 = ldu(ub, t0 - 1, uc1), a2 = ldu(ub, t0, uc1),
          a3 = ldu(ub, t0 + 1, uc1), a4 = ldu(ub, t0 + 2, uc1);
    float e0 = ldu(ub, t0 - 2, ucv), e1 = ldu(ub, t0 - 1, ucv), e2 = ldu(ub, t0, ucv),
          e3 = ldu(ub, t0 + 1, ucv), e4 = ldu(ub, t0 + 2, ucv);

    for (int base = 0; base < CHUNK; base += 8) {
        float an[8], en[8];
#pragma unroll
        for (int k = 0; k < 8; k++) {
            an[k] = ldu(ub, t0 + base + k + 3, uc1);
            en[k] = ldu(ub, t0 + base + k + 3, ucv);
        }
#pragma unroll
        for (int k = 0; k < 8; k++) {
            float z1 = fmaf(w1a, a0 + a4, fmaf(w1b, a1 + a3, w1c * a2));
            float zv = fmaf(wva, e0 + e4, fmaf(wvb, e1 + e3, wvc * e2));
            float x  = z1 * zv;
            xvp[(size_t)(t0 + base + k) * NHID] = x;
            u64 xx = pk2(x, x);
#pragma unroll
            for (int m = 0; m < 8; m++) Sf[m] = fma2_(p2[m], Sf[m], xx);
#pragma unroll
            for (int m = 0; m < 8; m++) { Sb[m] = fma2_(pw[m], xx, Sb[m]); pw[m] = mul2_(pw[m], p2[m]); }
            a0 = a1; a1 = a2; a2 = a3; a3 = a4; a4 = an[k];
            e0 = e1; e1 = e2; e2 = e3; e3 = e4; e4 = en[k];
        }
    }

    float* dst = g_carr + ((size_t)j * (NB * NHID) + (size_t)b * NHID + c) * 32;
#pragma unroll
    for (int m = 0; m < 8; m++) {
        float2 f = up2(Sf[m]); dst[2 * m]      = f.x; dst[2 * m + 1]      = f.y;
        float2 g = up2(Sb[m]); dst[16 + 2 * m] = g.x; dst[16 + 2 * m + 1] = g.y;
    }
}

// ---------------------------------------------------------------------------
// K2: in-place affine exclusive scan across chunks per (b,c,mode,dir).
// ---------------------------------------------------------------------------
__global__ void k2_scan(const float* __restrict__ logp)
{
    const int tid = blockIdx.x * blockDim.x + threadIdx.x;
    if (tid >= NB * NHID * 32) return;
    const int dirm = tid & 31;
    const int bc   = tid >> 5;
    const int m    = dirm & 15;
    const int dir  = dirm >> 4;
    const float q  = expf(logp[m] * (float)CHUNK);

    const size_t stride = (size_t)(NB * NHID) * 32;
    float* base = g_carr + (size_t)bc * 32 + dirm;
    float carry = 0.0f;
    if (dir == 0) {
        for (int j = 0; j < NCHUNK; j++) {
            float s = base[(size_t)j * stride];
            base[(size_t)j * stride] = carry;
            carry = fmaf(q, carry, s);
        }
    } else {
        for (int j = NCHUNK - 1; j >= 0; j--) {
            float s = base[(size_t)j * stride];
            base[(size_t)j * stride] = carry;
            carry = fmaf(q, carry, s);
        }
    }
}

// ---------------------------------------------------------------------------
// K3: descending sweep (backward recurrence over g_xv) -> smem partial,
//     ascending sweep (forward recurrence + x2 gate FIR) -> output.
// ---------------------------------------------------------------------------
__global__ void __launch_bounds__(CHB)
k3_apply(const float* __restrict__ u, const float* __restrict__ w,
         const float* __restrict__ logp, const float* __restrict__ resid,
         const float* __restrict__ Dp, float* __restrict__ out)
{
    __shared__ float ysm[CHUNK * CHB];   // 32 KB, thread-private columns

    const int j = blockIdx.x;
    const int c = blockIdx.y * CHB + threadIdx.x;
    const int b = blockIdx.z;
    const int hh = c >> 6, d = c & 63;
    const int uc2 = hh * 192 + d;        // x2 (gate)
    const float* ub  = u + (size_t)b * NL * USTR;
    const float* xvp = g_xv + ((size_t)b * NL) * NHID + c;

    const float w2a = w[uc2 * 3 + 0], w2b = w[uc2 * 3 + 1], w2c = 2.0f * w[uc2 * 3 + 2];

    u64 p2[8], r2[8];
#pragma unroll
    for (int m = 0; m < 8; m++) {
        p2[m] = pk2(expf(logp[2 * m]), expf(logp[2 * m + 1]));
        r2[m] = pk2(resid[2 * m], resid[2 * m + 1]);
    }
    const float Dc = Dp[c];

    const float* cp = g_carr + ((size_t)j * (NB * NHID) + (size_t)b * NHID + c) * 32;
    const int t0 = j * CHUNK;

    // ---- sweep 1: descending (backward recurrence) ----
    u64 Bk[8];
#pragma unroll
    for (int m = 0; m < 8; m++) Bk[m] = pk2(cp[16 + 2 * m], cp[16 + 2 * m + 1]);

    for (int base = CHUNK - 8; base >= 0; base -= 8) {
        float xs[8];
#pragma unroll
        for (int k = 0; k < 8; k++) xs[k] = xvp[(size_t)(t0 + base + k) * NHID];
#pragma unroll
        for (int k = 7; k >= 0; k--) {
            float x = xs[k];
            u64 xx = pk2(x, x);
#pragma unroll
            for (int m = 0; m < 8; m++) Bk[m] = fma2_(p2[m], Bk[m], xx);
            u64 ac0 = mul2_(r2[0], Bk[0]), ac1 = mul2_(r2[1], Bk[1]);
#pragma unroll
            for (int m = 2; m < 8; m += 2) {
                ac0 = fma2_(r2[m], Bk[m], ac0);
                ac1 = fma2_(r2[m + 1], Bk[m + 1], ac1);
            }
            float2 s = up2(add2_(ac0, ac1));
            ysm[(base + k) * CHB + threadIdx.x] = fmaf(Dc, x, s.x + s.y);
        }
    }

    // ---- sweep 2: ascending (forward recurrence + output gate) ----
    u64 F[8];
#pragma unroll
    for (int m = 0; m < 8; m++) F[m] = pk2(cp[2 * m], cp[2 * m + 1]);

    float g0 = ldu(ub, t0 - 2, uc2), g1 = ldu(ub, t0 - 1, uc2), g2 = ldu(ub, t0, uc2),
          g3 = ldu(ub, t0 + 1, uc2), g4 = ldu(ub, t0 + 2, uc2);
    float* op = out + ((size_t)b * NL + t0) * NHID + c;

    for (int base = 0; base < CHUNK; base += 8) {
        float xs[8], gs[8];
#pragma unroll
        for (int k = 0; k < 8; k++) {
            xs[k] = xvp[(size_t)(t0 + base + k) * NHID];
            gs[k] = ldu(ub, t0 + base + k + 3, uc2);
        }
#pragma unroll
        for (int k = 0; k < 8; k++) {
            float x = xs[k];
            u64 xx = pk2(x, x);
#pragma unroll
            for (int m = 0; m < 8; m++) F[m] = fma2_(p2[m], F[m], xx);
            u64 ac0 = mul2_(r2[0], F[0]), ac1 = mul2_(r2[1], F[1]);
#pragma unroll
            for (int m = 2; m < 8; m += 2) {
                ac0 = fma2_(r2[m], F[m], ac0);
                ac1 = fma2_(r2[m + 1], F[m + 1], ac1);
            }
            float2 s = up2(add2_(ac0, ac1));
            float z2 = fmaf(w2a, g0 + g4, fmaf(w2b, g1 + g3, w2c * g2));
            float y  = s.x + s.y + ysm[(base + k) * CHB + threadIdx.x];
            op[(size_t)(base + k) * NHID] = y * z2;
            g0 = g1; g1 = g2; g2 = g3; g3 = g4; g4 = gs[k];
        }
    }
}

// ---------------------------------------------------------------------------
extern "C" void kernel_launch(void* const* d_in, const int* in_sizes, int n_in,
                              void* d_out, int out_size)
{
    const float* u     = (const float*)d_in[0];
    const float* w     = (const float*)d_in[1];
    const float* logp  = (const float*)d_in[2];
    const float* resid = (const float*)d_in[3];
    const float* Dp    = (const float*)d_in[4];
    float* out = (float*)d_out;

    dim3 grid(NCHUNK, NHID / CHB, NB);   // (128, 8, 2)
    k1_chunk_sums<<<grid, CHB>>>(u, w, logp);

    const int nscan = NB * NHID * 32;    // 65536
    k2_scan<<<(nscan + 255) / 256, 256>>>(logp);

    k3_apply<<<grid, CHB>>>(u, w, logp, resid, Dp, out);
}